// round 16
// baseline (speedup 1.0000x reference)
#include <cuda_runtime.h>
#include <cuda_fp16.h>
#include <mma.h>
#include <cstdint>
#include <cstddef>

using namespace nvcuda;

#define HIDDEN   512
#define HEADS    8
#define HEAD_DIM 64
#define BATCH    4096
#define SEQ      16
#define NTOK     (BATCH * SEQ)   // 65536
#define NQKV     (3 * HIDDEN)    // 1536

#define NCH      4                       // pipeline chunks over batch
#define MCH      (NTOK / NCH)            // 16384 token-rows per chunk
#define BCH      (BATCH / NCH)           // 1024 batches per chunk

// ---- scratch (no allocs allowed; device globals are the sanctioned path) ----
__device__ __half g_xh  [(size_t)NTOK * HIDDEN];   // 64 MiB  fp16 input
__device__ __half g_wq  [(size_t)NQKV * HIDDEN];   // 1.5 MiB fp16 w_qkv
__device__ __half g_wo  [(size_t)HIDDEN * HIDDEN]; // 0.5 MiB fp16 w_o
__device__ __half g_qkvh[(size_t)NTOK * NQKV];     // 192 MiB fp16 qkv
__device__ __half g_attn[(size_t)NTOK * HIDDEN];   // 64 MiB  fp16 attn out

// ---------------------------------------------------------------------------
// cp.async helpers (LDGSTS, 16B)
// ---------------------------------------------------------------------------
__device__ __forceinline__ void cp_async16(void* smem, const void* gmem) {
    unsigned int s = (unsigned int)__cvta_generic_to_shared(smem);
    asm volatile("cp.async.cg.shared.global [%0], [%1], 16;\n" :: "r"(s), "l"(gmem));
}
__device__ __forceinline__ void cp_commit() {
    asm volatile("cp.async.commit_group;\n" ::: "memory");
}
template <int N>
__device__ __forceinline__ void cp_wait() {
    asm volatile("cp.async.wait_group %0;\n" :: "n"(N) : "memory");
}

// ---------------------------------------------------------------------------
// fp32 -> fp16 converters
// ---------------------------------------------------------------------------
__global__ void f2h_x_kernel(const float* __restrict__ in, size_t obase) {
    int i = 4 * (blockIdx.x * blockDim.x + threadIdx.x);   // within chunk
    float4 v = *reinterpret_cast<const float4*>(in + i);
    *reinterpret_cast<__half2*>(&g_xh[obase + i])     = __floats2half2_rn(v.x, v.y);
    *reinterpret_cast<__half2*>(&g_xh[obase + i + 2]) = __floats2half2_rn(v.z, v.w);
}
__global__ void f2h_wq_kernel(const float* __restrict__ in) {
    int i = 4 * (blockIdx.x * blockDim.x + threadIdx.x);
    if (i < NQKV * HIDDEN) {
        float4 v = *reinterpret_cast<const float4*>(in + i);
        *reinterpret_cast<__half2*>(&g_wq[i])     = __floats2half2_rn(v.x, v.y);
        *reinterpret_cast<__half2*>(&g_wq[i + 2]) = __floats2half2_rn(v.z, v.w);
    }
}
__global__ void f2h_wo_kernel(const float* __restrict__ in) {
    int i = 4 * (blockIdx.x * blockDim.x + threadIdx.x);
    if (i < HIDDEN * HIDDEN) {
        float4 v = *reinterpret_cast<const float4*>(in + i);
        *reinterpret_cast<__half2*>(&g_wo[i])     = __floats2half2_rn(v.x, v.y);
        *reinterpret_cast<__half2*>(&g_wo[i + 2]) = __floats2half2_rn(v.z, v.w);
    }
}

// ---------------------------------------------------------------------------
// GEMM: C[M,N] = A[M,K] * B[N,K]^T   (A,B fp16 K-contiguous; fp32 accum)
// CTA tile 128x128x32, 128 threads = 4 warps, warp tile 64x64 (2x2 grid).
// 2-stage cp.async double buffering. (Proven R7/R15 kernel.)
// m0 = chunk row offset.
// ---------------------------------------------------------------------------
template <bool HALF_OUT>
__device__ __forceinline__ void gemm_body(const __half* __restrict__ A,
                                          const __half* __restrict__ B,
                                          __half* __restrict__ Ch,
                                          float* __restrict__ Cf,
                                          int N, int K, int m0) {
    constexpr int BM = 128, BN = 128, BK = 32, LDS = BK + 8; // 40 halves = 80B rows
    __shared__ __align__(16) __half As[2][BM * LDS];
    __shared__ __align__(16) __half Bs[2][BN * LDS];

    const int bm   = m0 + blockIdx.y * BM;
    const int bn   = blockIdx.x * BN;
    const int tid  = threadIdx.x;
    const int warp = tid >> 5;
    const int wm   = (warp & 1) * 64;    // warp row offset in tile
    const int wn   = (warp >> 1) * 64;   // warp col offset in tile

    auto stage_load = [&](int kt, int buf) {
        #pragma unroll
        for (int l = 0; l < 4; l++) {
            int v  = tid + l * 128;
            int r  = v >> 2;
            int c8 = (v & 3) * 8;
            cp_async16(&As[buf][r * LDS + c8], &A[(size_t)(bm + r) * K + kt + c8]);
            cp_async16(&Bs[buf][r * LDS + c8], &B[(size_t)(bn + r) * K + kt + c8]);
        }
        cp_commit();
    };

    wmma::fragment<wmma::accumulator, 16, 16, 16, float> acc[4][4];
    #pragma unroll
    for (int i = 0; i < 4; i++)
        #pragma unroll
        for (int j = 0; j < 4; j++) wmma::fill_fragment(acc[i][j], 0.0f);

    const int nst = K / BK;
    stage_load(0, 0);

    for (int s = 0; s < nst; s++) {
        cp_wait<0>();
        __syncthreads();
        if (s + 1 < nst) stage_load((s + 1) * BK, (s + 1) & 1);

        const __half* as = As[s & 1];
        const __half* bs = Bs[s & 1];
        #pragma unroll
        for (int kk = 0; kk < BK; kk += 16) {
            wmma::fragment<wmma::matrix_a, 16, 16, 16, __half, wmma::row_major> af[4];
            wmma::fragment<wmma::matrix_b, 16, 16, 16, __half, wmma::col_major> bf[4];
            #pragma unroll
            for (int i = 0; i < 4; i++)
                wmma::load_matrix_sync(af[i], &as[(wm + i * 16) * LDS + kk], LDS);
            #pragma unroll
            for (int j = 0; j < 4; j++)
                wmma::load_matrix_sync(bf[j], &bs[(wn + j * 16) * LDS + kk], LDS);
            #pragma unroll
            for (int i = 0; i < 4; i++)
                #pragma unroll
                for (int j = 0; j < 4; j++)
                    wmma::mma_sync(acc[i][j], af[i], bf[j], acc[i][j]);
        }
    }

    #pragma unroll
    for (int i = 0; i < 4; i++) {
        #pragma unroll
        for (int j = 0; j < 4; j++) {
            if (HALF_OUT) {
                wmma::fragment<wmma::accumulator, 16, 16, 16, __half> hf;
                #pragma unroll
                for (int e = 0; e < hf.num_elements; e++)
                    hf.x[e] = __float2half(acc[i][j].x[e]);
                wmma::store_matrix_sync(&Ch[(size_t)(bm + wm + i * 16) * N + bn + wn + j * 16],
                                        hf, N, wmma::mem_row_major);
            } else {
                wmma::store_matrix_sync(&Cf[(size_t)(bm + wm + i * 16) * N + bn + wn + j * 16],
                                        acc[i][j], N, wmma::mem_row_major);
            }
        }
    }
}

__global__ __launch_bounds__(128) void gemm_qkv_kernel(int m0) {
    gemm_body<true>(g_xh, g_wq, g_qkvh, nullptr, NQKV, HIDDEN, m0);
}
__global__ __launch_bounds__(128) void gemm_out_kernel(float* __restrict__ C, int m0) {
    gemm_body<false>(g_attn, g_wo, nullptr, C, HIDDEN, HIDDEN, m0);
}

// ---------------------------------------------------------------------------
// Attention (R15 fp16-smem version): one block per (batch, head).
// ---------------------------------------------------------------------------
#define ALD 68   // padded row length in halves

__global__ __launch_bounds__(128) void attn_kernel(int b0) {
    const int b = b0 + (blockIdx.x >> 3);
    const int h = blockIdx.x & 7;
    const size_t base = (size_t)b * SEQ;
    const int tid = threadIdx.x;

    __shared__ __half sq[SEQ][ALD], sk[SEQ][ALD], sv[SEQ][ALD];
    __shared__ float  sp[SEQ][SEQ + 1];

    #pragma unroll
    for (int l = 0; l < 3; l++) {
        int s  = tid >> 3;
        int d8 = (tid & 7) * 8;
        int4 raw = *reinterpret_cast<const int4*>(
            &g_qkvh[(base + s) * NQKV + l * HIDDEN + h * HEAD_DIM + d8]);
        __half* dst = (l == 0) ? &sq[s][d8] : (l == 1) ? &sk[s][d8] : &sv[s][d8];
        const uint2* u = reinterpret_cast<const uint2*>(&raw);
        reinterpret_cast<uint2*>(dst)[0] = u[0];
        reinterpret_cast<uint2*>(dst)[1] = u[1];
    }
    __syncthreads();

    #pragma unroll
    for (int l = 0; l < 2; l++) {
        int sidx = tid + l * 128;
        int i = sidx >> 4, j = sidx & 15;
        float a = 0.f;
        #pragma unroll
        for (int c = 0; c < 16; c++) {
            uint2 qu = *reinterpret_cast<const uint2*>(&sq[i][c * 4]);
            uint2 ku = *reinterpret_cast<const uint2*>(&sk[j][c * 4]);
            float2 q0 = __half22float2(*reinterpret_cast<const __half2*>(&qu.x));
            float2 q1 = __half22float2(*reinterpret_cast<const __half2*>(&qu.y));
            float2 k0 = __half22float2(*reinterpret_cast<const __half2*>(&ku.x));
            float2 k1 = __half22float2(*reinterpret_cast<const __half2*>(&ku.y));
            a += q0.x * k0.x + q0.y * k0.y + q1.x * k1.x + q1.y * k1.y;
        }
        sp[i][j] = a * 0.125f;
    }
    __syncthreads();

    if (tid < SEQ) {
        float m = sp[tid][0];
        #pragma unroll
        for (int j = 1; j < SEQ; j++) m = fmaxf(m, sp[tid][j]);
        float e[SEQ], s = 0.f;
        #pragma unroll
        for (int j = 0; j < SEQ; j++) { e[j] = expf(sp[tid][j] - m); s += e[j]; }
        float inv = 1.0f / s;
        #pragma unroll
        for (int j = 0; j < SEQ; j++) sp[tid][j] = e[j] * inv;
    }
    __syncthreads();

    #pragma unroll
    for (int l = 0; l < 2; l++) {
        int o  = tid + l * 128;
        int i  = o >> 4;
        int c4 = (o & 15) * 4;
        float a0 = 0.f, a1 = 0.f, a2 = 0.f, a3 = 0.f;
        #pragma unroll
        for (int j = 0; j < SEQ; j++) {
            float p = sp[i][j];
            uint2 vu = *reinterpret_cast<const uint2*>(&sv[j][c4]);
            float2 v0 = __half22float2(*reinterpret_cast<const __half2*>(&vu.x));
            float2 v1 = __half22float2(*reinterpret_cast<const __half2*>(&vu.y));
            a0 += p * v0.x; a1 += p * v0.y; a2 += p * v1.x; a3 += p * v1.y;
        }
        uint2 w;
        *reinterpret_cast<__half2*>(&w.x) = __floats2half2_rn(a0, a1);
        *reinterpret_cast<__half2*>(&w.y) = __floats2half2_rn(a2, a3);
        *reinterpret_cast<uint2*>(&g_attn[(base + i) * HIDDEN + h * HEAD_DIM + c4]) = w;
    }
}

// ---------------------------------------------------------------------------
// Launch: fork-join two-stream pipeline (capture-legal pattern).
//   origin stream (legacy 0): weight converts, qkv GEMM chunks, o-proj chunks
//   side stream s1          : x converts, attention chunks
// Deps via events: f2h(c) -> qkv(c) -> attn(c) -> out(c)
// ---------------------------------------------------------------------------
static cudaStream_t g_s1;
static cudaEvent_t  g_evRoot, g_evF2h[NCH], g_evQkv[NCH], g_evAttn[NCH];
static bool g_init = false;

extern "C" void kernel_launch(void* const* d_in, const int* in_sizes, int n_in,
                              void* d_out, int out_size) {
    const float* x    = (const float*)d_in[0];   // [4096,16,512]
    const float* wqkv = (const float*)d_in[1];   // [1536,512]
    const float* wo   = (const float*)d_in[2];   // [512,512]
    float* out        = (float*)d_out;           // [4096,16,512]

    if (!g_init) {
        cudaStreamCreateWithFlags(&g_s1, cudaStreamNonBlocking);
        cudaEventCreateWithFlags(&g_evRoot, cudaEventDisableTiming);
        for (int c = 0; c < NCH; c++) {
            cudaEventCreateWithFlags(&g_evF2h[c],  cudaEventDisableTiming);
            cudaEventCreateWithFlags(&g_evQkv[c],  cudaEventDisableTiming);
            cudaEventCreateWithFlags(&g_evAttn[c], cudaEventDisableTiming);
        }
        g_init = true;
    }

    // weight converts on origin stream (needed by both GEMM chains)
    f2h_wq_kernel<<<(NQKV * HIDDEN) / 1024, 256>>>(wqkv);
    f2h_wo_kernel<<<(HIDDEN * HIDDEN) / 1024, 256>>>(wo);

    // fork side stream from origin
    cudaEventRecord(g_evRoot, 0);
    cudaStreamWaitEvent(g_s1, g_evRoot, 0);

    // side stream: x conversion chunks
    for (int c = 0; c < NCH; c++) {
        const size_t eoff = (size_t)c * MCH * HIDDEN;    // elements per chunk: 8M
        f2h_x_kernel<<<(MCH * HIDDEN) / 1024, 256, 0, g_s1>>>(x + eoff, eoff);
        cudaEventRecord(g_evF2h[c], g_s1);
    }

    // origin stream: QKV GEMM chunks
    for (int c = 0; c < NCH; c++) {
        cudaStreamWaitEvent(0, g_evF2h[c], 0);
        dim3 grid(NQKV / 128, MCH / 128);
        gemm_qkv_kernel<<<grid, 128>>>(c * MCH);
        cudaEventRecord(g_evQkv[c], 0);
    }

    // side stream: attention chunks
    for (int c = 0; c < NCH; c++) {
        cudaStreamWaitEvent(g_s1, g_evQkv[c], 0);
        attn_kernel<<<BCH * HEADS, 128, 0, g_s1>>>(c * BCH);
        cudaEventRecord(g_evAttn[c], g_s1);
    }

    // origin stream: O-proj chunks (joins side stream back into origin)
    for (int c = 0; c < NCH; c++) {
        cudaStreamWaitEvent(0, g_evAttn[c], 0);
        dim3 grid(HIDDEN / 128, MCH / 128);
        gemm_out_kernel<<<grid, 128>>>(out, c * MCH);
    }
}

// round 17
// speedup vs baseline: 1.1187x; 1.1187x over previous
#include <cuda_runtime.h>
#include <cuda_fp16.h>
#include <mma.h>
#include <cstdint>

using namespace nvcuda;

#define HIDDEN   512
#define HEADS    8
#define HEAD_DIM 64
#define BATCH    4096
#define SEQ      16
#define NTOK     (BATCH * SEQ)   // 65536
#define NQKV     (3 * HIDDEN)    // 1536

// ---- scratch (no allocs allowed; device globals are the sanctioned path) ----
__device__ __half g_xh  [(size_t)NTOK * HIDDEN];   // 64 MiB  fp16 input
__device__ __half g_wq  [(size_t)NQKV * HIDDEN];   // 1.5 MiB fp16 w_qkv
__device__ __half g_wo  [(size_t)HIDDEN * HIDDEN]; // 0.5 MiB fp16 w_o
__device__ __half g_qkvh[(size_t)NTOK * NQKV];     // 192 MiB fp16 qkv
__device__ __half g_attn[(size_t)NTOK * HIDDEN];   // 64 MiB  fp16 attn out

// ---------------------------------------------------------------------------
// cp.async helpers (LDGSTS, 16B)
// ---------------------------------------------------------------------------
__device__ __forceinline__ void cp_async16(void* smem, const void* gmem) {
    unsigned int s = (unsigned int)__cvta_generic_to_shared(smem);
    asm volatile("cp.async.cg.shared.global [%0], [%1], 16;\n" :: "r"(s), "l"(gmem));
}
__device__ __forceinline__ void cp_commit() {
    asm volatile("cp.async.commit_group;\n" ::: "memory");
}
template <int N>
__device__ __forceinline__ void cp_wait() {
    asm volatile("cp.async.wait_group %0;\n" :: "n"(N) : "memory");
}

// ---------------------------------------------------------------------------
// fp32 -> fp16 converters (n always multiple of 4)
// ---------------------------------------------------------------------------
__device__ __forceinline__ void f2h_body(const float* __restrict__ in,
                                         __half* __restrict__ out, int n) {
    int i = 4 * (blockIdx.x * blockDim.x + threadIdx.x);
    if (i < n) {
        float4 v = *reinterpret_cast<const float4*>(in + i);
        *reinterpret_cast<__half2*>(out + i)     = __floats2half2_rn(v.x, v.y);
        *reinterpret_cast<__half2*>(out + i + 2) = __floats2half2_rn(v.z, v.w);
    }
}
__global__ void f2h_x_kernel (const float* __restrict__ in) { f2h_body(in, g_xh, NTOK * HIDDEN); }
__global__ void f2h_wq_kernel(const float* __restrict__ in) { f2h_body(in, g_wq, NQKV * HIDDEN); }
__global__ void f2h_wo_kernel(const float* __restrict__ in) { f2h_body(in, g_wo, HIDDEN * HIDDEN); }

// ---------------------------------------------------------------------------
// GEMM: C[M,N] = A[M,K] * B[N,K]^T   (A,B fp16 K-contiguous; fp32 accum)
// CTA tile 128x128x32, 128 threads = 4 warps, warp tile 64x64 (2x2 grid).
// 2-stage cp.async double buffering. (Proven R7/R15 kernel.)
// ---------------------------------------------------------------------------
template <bool HALF_OUT>
__device__ __forceinline__ void gemm_body(const __half* __restrict__ A,
                                          const __half* __restrict__ B,
                                          __half* __restrict__ Ch,
                                          float* __restrict__ Cf,
                                          int N, int K) {
    constexpr int BM = 128, BN = 128, BK = 32, LDS = BK + 8; // 40 halves = 80B rows
    __shared__ __align__(16) __half As[2][BM * LDS];
    __shared__ __align__(16) __half Bs[2][BN * LDS];

    const int bm   = blockIdx.y * BM;
    const int bn   = blockIdx.x * BN;
    const int tid  = threadIdx.x;
    const int warp = tid >> 5;
    const int wm   = (warp & 1) * 64;    // warp row offset in tile
    const int wn   = (warp >> 1) * 64;   // warp col offset in tile

    auto stage_load = [&](int kt, int buf) {
        #pragma unroll
        for (int l = 0; l < 4; l++) {
            int v  = tid + l * 128;
            int r  = v >> 2;
            int c8 = (v & 3) * 8;
            cp_async16(&As[buf][r * LDS + c8], &A[(size_t)(bm + r) * K + kt + c8]);
            cp_async16(&Bs[buf][r * LDS + c8], &B[(size_t)(bn + r) * K + kt + c8]);
        }
        cp_commit();
    };

    wmma::fragment<wmma::accumulator, 16, 16, 16, float> acc[4][4];
    #pragma unroll
    for (int i = 0; i < 4; i++)
        #pragma unroll
        for (int j = 0; j < 4; j++) wmma::fill_fragment(acc[i][j], 0.0f);

    const int nst = K / BK;
    stage_load(0, 0);

    for (int s = 0; s < nst; s++) {
        cp_wait<0>();
        __syncthreads();
        if (s + 1 < nst) stage_load((s + 1) * BK, (s + 1) & 1);

        const __half* as = As[s & 1];
        const __half* bs = Bs[s & 1];
        #pragma unroll
        for (int kk = 0; kk < BK; kk += 16) {
            wmma::fragment<wmma::matrix_a, 16, 16, 16, __half, wmma::row_major> af[4];
            wmma::fragment<wmma::matrix_b, 16, 16, 16, __half, wmma::col_major> bf[4];
            #pragma unroll
            for (int i = 0; i < 4; i++)
                wmma::load_matrix_sync(af[i], &as[(wm + i * 16) * LDS + kk], LDS);
            #pragma unroll
            for (int j = 0; j < 4; j++)
                wmma::load_matrix_sync(bf[j], &bs[(wn + j * 16) * LDS + kk], LDS);
            #pragma unroll
            for (int i = 0; i < 4; i++)
                #pragma unroll
                for (int j = 0; j < 4; j++)
                    wmma::mma_sync(acc[i][j], af[i], bf[j], acc[i][j]);
        }
    }

    #pragma unroll
    for (int i = 0; i < 4; i++) {
        #pragma unroll
        for (int j = 0; j < 4; j++) {
            if (HALF_OUT) {
                wmma::fragment<wmma::accumulator, 16, 16, 16, __half> hf;
                #pragma unroll
                for (int e = 0; e < hf.num_elements; e++)
                    hf.x[e] = __float2half(acc[i][j].x[e]);
                wmma::store_matrix_sync(&Ch[(size_t)(bm + wm + i * 16) * N + bn + wn + j * 16],
                                        hf, N, wmma::mem_row_major);
            } else {
                wmma::store_matrix_sync(&Cf[(size_t)(bm + wm + i * 16) * N + bn + wn + j * 16],
                                        acc[i][j], N, wmma::mem_row_major);
            }
        }
    }
}

__global__ __launch_bounds__(128) void gemm_qkv_kernel() {
    gemm_body<true>(g_xh, g_wq, g_qkvh, nullptr, NQKV, HIDDEN);
}
__global__ __launch_bounds__(128) void gemm_out_kernel(float* __restrict__ C) {
    gemm_body<false>(g_attn, g_wo, nullptr, C, HIDDEN, HIDDEN);
}

// ---------------------------------------------------------------------------
// Attention v3 (tensor-core): block = 128 threads = 4 warps = 4 heads of one
// batch; grid = BATCH*2 (head groups 0-3 and 4-7). Each warp privately:
//   QK^T via 4x wmma (fp32 acc), scale, exact fp32 softmax (16 lanes),
//   P -> fp16, PV via 4x wmma, fp16 fragment store straight to g_attn.
// Per-warp smem regions are disjoint -> __syncwarp() only.
// ---------------------------------------------------------------------------
__global__ __launch_bounds__(128) void attn_kernel() {
    const int b    = blockIdx.x >> 1;
    const int hg   = (blockIdx.x & 1) * 4;
    const int wid  = threadIdx.x >> 5;
    const int lane = threadIdx.x & 31;
    const int h    = hg + wid;
    const size_t base = (size_t)b * SEQ;

    __shared__ __half sq[4][16][72], sk[4][16][72], sv[4][16][72]; // ld=72: conflict-free ldmatrix
    __shared__ float  sp [4][16][20];
    __shared__ __half spt[4][16][24];

    // load q,k,v for this warp's head: 3 x 16 rows x 64 halves, uint4 chunks
    #pragma unroll
    for (int sel = 0; sel < 3; sel++) {
        __half (*dst)[72] = (sel == 0) ? sq[wid] : (sel == 1) ? sk[wid] : sv[wid];
        const size_t gbase = base * NQKV + (size_t)sel * HIDDEN + (size_t)h * HEAD_DIM;
        #pragma unroll
        for (int l = 0; l < 4; l++) {
            int idx = lane + l * 32;       // 0..127: row = idx/8, 16B chunk = idx%8
            int s   = idx >> 3;
            int c8  = (idx & 7) * 8;
            *reinterpret_cast<uint4*>(&dst[s][c8]) =
                *reinterpret_cast<const uint4*>(&g_qkvh[gbase + (size_t)s * NQKV + c8]);
        }
    }
    __syncwarp();

    // scores = Q K^T / 8   (16x16, fp32 acc)
    wmma::fragment<wmma::accumulator, 16, 16, 16, float> sacc;
    wmma::fill_fragment(sacc, 0.0f);
    #pragma unroll
    for (int kk = 0; kk < HEAD_DIM; kk += 16) {
        wmma::fragment<wmma::matrix_a, 16, 16, 16, __half, wmma::row_major> qa;
        wmma::fragment<wmma::matrix_b, 16, 16, 16, __half, wmma::col_major> kb;
        wmma::load_matrix_sync(qa, &sq[wid][0][kk], 72);
        wmma::load_matrix_sync(kb, &sk[wid][0][kk], 72);
        wmma::mma_sync(sacc, qa, kb, sacc);
    }
    #pragma unroll
    for (int e = 0; e < sacc.num_elements; e++) sacc.x[e] *= 0.125f;
    wmma::store_matrix_sync(&sp[wid][0][0], sacc, 20, wmma::mem_row_major);
    __syncwarp();

    // exact fp32 softmax, one lane per row; P written fp16
    if (lane < 16) {
        float m = sp[wid][lane][0];
        #pragma unroll
        for (int j = 1; j < 16; j++) m = fmaxf(m, sp[wid][lane][j]);
        float e[16], s = 0.f;
        #pragma unroll
        for (int j = 0; j < 16; j++) { e[j] = expf(sp[wid][lane][j] - m); s += e[j]; }
        float inv = 1.0f / s;
        #pragma unroll
        for (int j = 0; j < 16; j++) spt[wid][lane][j] = __float2half(e[j] * inv);
    }
    __syncwarp();

    // out = P V  (16x64 via 4 n-tiles), fp16 fragment store to gmem
    wmma::fragment<wmma::matrix_a, 16, 16, 16, __half, wmma::row_major> pa;
    wmma::load_matrix_sync(pa, &spt[wid][0][0], 24);
    #pragma unroll
    for (int nt = 0; nt < 4; nt++) {
        wmma::fragment<wmma::matrix_b, 16, 16, 16, __half, wmma::row_major> vb;
        wmma::fragment<wmma::accumulator, 16, 16, 16, float> oacc;
        wmma::fill_fragment(oacc, 0.0f);
        wmma::load_matrix_sync(vb, &sv[wid][0][nt * 16], 72);
        wmma::mma_sync(oacc, pa, vb, oacc);
        wmma::fragment<wmma::accumulator, 16, 16, 16, __half> oh;
        #pragma unroll
        for (int e = 0; e < oh.num_elements; e++) oh.x[e] = __float2half(oacc.x[e]);
        wmma::store_matrix_sync(&g_attn[base * HIDDEN + (size_t)h * HEAD_DIM + nt * 16],
                                oh, HIDDEN, wmma::mem_row_major);
    }
}

// ---------------------------------------------------------------------------
extern "C" void kernel_launch(void* const* d_in, const int* in_sizes, int n_in,
                              void* d_out, int out_size) {
    const float* x    = (const float*)d_in[0];   // [4096,16,512]
    const float* wqkv = (const float*)d_in[1];   // [1536,512]
    const float* wo   = (const float*)d_in[2];   // [512,512]
    float* out        = (float*)d_out;           // [4096,16,512]

    f2h_x_kernel <<<(NTOK * HIDDEN) / 1024, 256>>>(x);
    f2h_wq_kernel<<<(NQKV * HIDDEN) / 1024, 256>>>(wqkv);
    f2h_wo_kernel<<<(HIDDEN * HIDDEN) / 1024, 256>>>(wo);

    {   // QKV: [65536,512] x [512,1536]
        dim3 grid(NQKV / 128, NTOK / 128);
        gemm_qkv_kernel<<<grid, 128>>>();
    }

    attn_kernel<<<BATCH * 2, 128>>>();

    {   // O-proj: [65536,512] x [512,512]
        dim3 grid(HIDDEN / 128, NTOK / 128);
        gemm_out_kernel<<<grid, 128>>>(out);
    }
}